// round 9
// baseline (speedup 1.0000x reference)
#include <cuda_runtime.h>
#include <math_constants.h>

#define N_NODES 50000
#define N_EDGES 800000
#define DIM 64
#define NCHUNK 98          // 98*512 = 50176 >= 50000 ; co-resident for lookback scan
#define NQ (N_EDGES / 4)
#define NHALF (NQ / 2)

// ---- device scratch (no allocations allowed; static zero-init) ----
__device__ int   g_counts[N_NODES];      // invariant: zero at entry of every replay
__device__ int   g_offsets[N_NODES + 1];
__device__ int   g_cursor[N_NODES];
__device__ int   g_csum[NCHUNK];
__device__ volatile int g_cflag[NCHUNK]; // invariant: zero at entry (reset by k_scatter)
__device__ int   g_srcidx[N_EDGES];
__device__ float g_h0[N_NODES * DIM];
__device__ float g_h1[N_NODES * DIM];

// ---- packed f32x2 helpers (Blackwell FFMA2 path, PTX-only) ----
__device__ __forceinline__ unsigned long long pk2(float lo, float hi) {
    unsigned long long r;
    asm("mov.b64 %0, {%1, %2};" : "=l"(r) : "f"(lo), "f"(hi));
    return r;
}
__device__ __forceinline__ void fma2(unsigned long long& d,
                                     unsigned long long a,
                                     unsigned long long b) {
    asm("fma.rn.f32x2 %0, %1, %2, %0;" : "+l"(d) : "l"(a), "l"(b));
}
__device__ __forceinline__ void upk2(float& lo, float& hi, unsigned long long v) {
    asm("mov.b64 {%0, %1}, %2;" : "=f"(lo), "=f"(hi) : "l"(v));
}

// ---------------- CSR build ----------------

__global__ void k_count(const int* __restrict__ dst) {
    int i = blockIdx.x * blockDim.x + threadIdx.x;
    if (i < NHALF) {
        int4 a = __ldg((const int4*)dst + i);
        int4 b = __ldg((const int4*)dst + i + NHALF);
        atomicAdd(&g_counts[a.x], 1);
        atomicAdd(&g_counts[a.y], 1);
        atomicAdd(&g_counts[a.z], 1);
        atomicAdd(&g_counts[a.w], 1);
        atomicAdd(&g_counts[b.x], 1);
        atomicAdd(&g_counts[b.y], 1);
        atomicAdd(&g_counts[b.z], 1);
        atomicAdd(&g_counts[b.w], 1);
    }
}

// single-kernel scan via decoupled lookback (all 98 blocks co-resident)
__global__ void __launch_bounds__(512) k_scan() {
    __shared__ int warp_sums[16];
    __shared__ int prefix_s;
    const int t = threadIdx.x, lane = t & 31, wid = t >> 5;
    const int c = blockIdx.x;
    const int i = c * 512 + t;

    int v = (i < N_NODES) ? g_counts[i] : 0;
    int s = v;
    #pragma unroll
    for (int d = 1; d < 32; d <<= 1) {
        int y = __shfl_up_sync(0xffffffffu, s, d);
        if (lane >= d) s += y;
    }
    if (lane == 31) warp_sums[wid] = s;
    __syncthreads();
    if (wid == 0 && lane < 16) {
        int ws = warp_sums[lane];
        #pragma unroll
        for (int d = 1; d < 16; d <<= 1) {
            int y = __shfl_up_sync(0xffffu, ws, d);
            if (lane >= d) ws += y;
        }
        warp_sums[lane] = ws;
    }
    __syncthreads();
    int excl = s - v + (wid > 0 ? warp_sums[wid - 1] : 0);

    if (t == 511) {
        g_csum[c] = excl + v;
        __threadfence();
        g_cflag[c] = 1;
    }
    if (t < 32) {
        int acc = 0;
        for (int j = lane; j < c; j += 32) {
            while (g_cflag[j] == 0) { }
            acc += *(volatile int*)&g_csum[j];
        }
        #pragma unroll
        for (int d = 16; d > 0; d >>= 1) acc += __shfl_down_sync(0xffffffffu, acc, d);
        if (lane == 0) prefix_s = acc;
    }
    __syncthreads();
    int prefix = prefix_s;

    if (i < N_NODES) {
        int o = excl + prefix;
        g_offsets[i] = o;
        g_cursor[i]  = o;
        g_counts[i]  = 0;
    }
    if (c == NCHUNK - 1 && t == 511)
        g_offsets[N_NODES] = prefix + excl + v;
}

__global__ void k_scatter(const int* __restrict__ src, const int* __restrict__ dst) {
    int i = blockIdx.x * blockDim.x + threadIdx.x;
    if (i < NCHUNK) g_cflag[i] = 0;
    if (i < NHALF) {
        int4 sa = __ldg((const int4*)src + i);
        int4 da = __ldg((const int4*)dst + i);
        int4 sb = __ldg((const int4*)src + i + NHALF);
        int4 db = __ldg((const int4*)dst + i + NHALF);
        g_srcidx[atomicAdd(&g_cursor[da.x], 1)] = sa.x;
        g_srcidx[atomicAdd(&g_cursor[da.y], 1)] = sa.y;
        g_srcidx[atomicAdd(&g_cursor[da.z], 1)] = sa.z;
        g_srcidx[atomicAdd(&g_cursor[da.w], 1)] = sa.w;
        g_srcidx[atomicAdd(&g_cursor[db.x], 1)] = sb.x;
        g_srcidx[atomicAdd(&g_cursor[db.y], 1)] = sb.y;
        g_srcidx[atomicAdd(&g_cursor[db.z], 1)] = sb.z;
        g_srcidx[atomicAdd(&g_cursor[db.w], 1)] = sb.w;
    }
}

// ---------------- fused layer: agg (segment-max) + GEMM + bias + leaky-relu ----
// 512 threads, tile = 64 nodes, warp per 4 nodes END-TO-END (no inter-phase sync).
// Agg: warp per node, float2 gathers (lane holds dims 2l,2l+1) -> X stays in regs.
// GEMM: x_k broadcast via shfl from owner lane k>>1; each lane computes cols
//       (2l, 2l+1) for the warp's 4 nodes with packed f32x2 FMA.
//       W read = ONE LDS.64 per warp per k (shared across all 4 nodes).
__global__ void __launch_bounds__(512, 3) k_layer(
        const float* __restrict__ h,
        const float* __restrict__ W,
        const float* __restrict__ bias,
        const float* __restrict__ eps, int layer,
        float* __restrict__ out, int activate) {
    __shared__ float Ws[64 * 64];     // [k][j]

    int t = threadIdx.x;              // 0..511
    int base = blockIdx.x * 64;

    // load W via float4 (1024 float4 over 512 threads); single sync of the kernel
    const float4* W4 = (const float4*)W;
    float4* Ws4 = (float4*)Ws;
    Ws4[t]       = W4[t];
    Ws4[t + 512] = W4[t + 512];

    float ep = 1.0f + __ldg(eps + layer);
    int warp = t >> 5, lane = t & 31;

    __syncthreads();                  // Ws visible to all warps

    // ---- phase 1: aggregation (per-warp, results stay in registers) ----
    float2 xr[4];
    #pragma unroll
    for (int q = 0; q < 4; q++) {
        int n = base + warp * 4 + q;
        int beg = 0, end = 0;
        if (n < N_NODES) { beg = g_offsets[n]; end = g_offsets[n + 1]; }
        float m0 = -CUDART_INF_F, m1 = -CUDART_INF_F;
        int i = beg;
        int cur[8];
        bool have = (i + 8 <= end);
        if (have) {
            #pragma unroll
            for (int u = 0; u < 8; u++) cur[u] = __ldg(&g_srcidx[i + u]);
        }
        while (have) {
            int ni = i + 8;
            bool nhave = (ni + 8 <= end);
            int nxt[8];
            if (nhave) {
                #pragma unroll
                for (int u = 0; u < 8; u++) nxt[u] = __ldg(&g_srcidx[ni + u]);
            }
            float2 a[8];
            #pragma unroll
            for (int u = 0; u < 8; u++)
                a[u] = __ldg((const float2*)(h + (size_t)cur[u] * DIM) + lane);
            #pragma unroll
            for (int u = 0; u < 8; u++) {
                m0 = fmaxf(m0, a[u].x);
                m1 = fmaxf(m1, a[u].y);
            }
            i = ni;
            #pragma unroll
            for (int u = 0; u < 8; u++) cur[u] = nxt[u];
            have = nhave;
        }
        for (; i < end; ++i) {
            int s = __ldg(&g_srcidx[i]);
            float2 a = __ldg((const float2*)(h + (size_t)s * DIM) + lane);
            m0 = fmaxf(m0, a.x);
            m1 = fmaxf(m1, a.y);
        }
        if (beg == end) { m0 = 0.0f; m1 = 0.0f; }   // DGL zero-fill
        if (n < N_NODES) {
            float2 hs = __ldg((const float2*)(h + (size_t)n * DIM) + lane);
            xr[q].x = fmaf(ep, hs.x, m0);
            xr[q].y = fmaf(ep, hs.y, m1);
        } else {
            xr[q].x = 0.0f; xr[q].y = 0.0f;
        }
    }

    // ---- phase 2: per-warp GEMM, x broadcast by shuffle, no smem X ----
    float2 bv = __ldg((const float2*)bias + lane);   // cols 2l, 2l+1
    unsigned long long bpk = pk2(bv.x, bv.y);
    unsigned long long acc[4];
    #pragma unroll
    for (int q = 0; q < 4; q++) acc[q] = bpk;

    const unsigned long long* Wp = (const unsigned long long*)Ws;  // [k][32 pairs]

    #pragma unroll
    for (int k = 0; k < 64; k++) {
        unsigned long long w = Wp[k * 32 + lane];    // (W[k][2l], W[k][2l+1])
        const int owner = k >> 1;
        #pragma unroll
        for (int q = 0; q < 4; q++) {
            float xs = (k & 1) ? xr[q].y : xr[q].x;
            float xk = __shfl_sync(0xffffffffu, xs, owner);
            fma2(acc[q], pk2(xk, xk), w);
        }
    }

    // ---- store: lane writes cols (2l, 2l+1) of its 4 nodes ----
    #pragma unroll
    for (int q = 0; q < 4; q++) {
        int n = base + warp * 4 + q;
        if (n < N_NODES) {
            float2 v;
            upk2(v.x, v.y, acc[q]);
            if (activate) {
                v.x = v.x >= 0.f ? v.x : 0.01f * v.x;
                v.y = v.y >= 0.f ? v.y : 0.01f * v.y;
            }
            *(float2*)&out[(size_t)n * DIM + lane * 2] = v;
        }
    }
}

// ---------------- launch ----------------
extern "C" void kernel_launch(void* const* d_in, const int* in_sizes, int n_in,
                              void* d_out, int out_size) {
    const float* n_feat = (const float*)d_in[0];
    const float* W0 = (const float*)d_in[1];
    const float* b0 = (const float*)d_in[2];
    const float* W1 = (const float*)d_in[3];
    const float* b1 = (const float*)d_in[4];
    const float* W2 = (const float*)d_in[5];
    const float* b2 = (const float*)d_in[6];
    const float* eps = (const float*)d_in[7];
    const int*   src = (const int*)d_in[8];
    const int*   dst = (const int*)d_in[9];
    float* out = (float*)d_out;

    float *h0_ptr, *h1_ptr;
    cudaGetSymbolAddress((void**)&h0_ptr, g_h0);
    cudaGetSymbolAddress((void**)&h1_ptr, g_h1);

    // CSR build (3 launches)
    k_count<<<(NHALF + 255) / 256, 256>>>(dst);
    k_scan<<<NCHUNK, 512>>>();
    k_scatter<<<(NHALF + 255) / 256, 256>>>(src, dst);

    const int layer_blocks = (N_NODES + 63) / 64;   // 782

    k_layer<<<layer_blocks, 512>>>(n_feat, W0, b0, eps, 0, h0_ptr, 1);
    k_layer<<<layer_blocks, 512>>>(h0_ptr, W1, b1, eps, 1, h1_ptr, 1);
    k_layer<<<layer_blocks, 512>>>(h1_ptr, W2, b2, eps, 2, out, 0);
}